// round 14
// baseline (speedup 1.0000x reference)
#include <cuda_runtime.h>
#include <cuda_fp16.h>
#include <mma.h>
#include <cstdint>

using namespace nvcuda;

namespace {
constexpr int E_TOT   = 100000;
constexpr int NSM     = 152;
constexpr int MT      = 16;                       // rows per pipeline tile
constexpr int TILES   = E_TOT / MT;               // 6250 exact
constexpr int NPIPE   = 4;
constexpr int NWORK   = NSM * NPIPE;              // 608 pipelines
constexpr int THREADS = 512;

// leading dims (elements)
constexpr int LDW0 = 136;   // halves
constexpr int LDW1 = 136;   // halves
constexpr int LDP  = 328;   // halves
constexpr int LDE  = 72;    // halves
constexpr int LDH  = 136;   // halves
constexpr int LDXH = 328;   // halves (w buffer, fp16 now)

// byte offsets
constexpr int O_W0 = 0;                           // 17408
constexpr int O_W1 = O_W0 + 64  * LDW0 * 2;       // 17408
constexpr int O_P  = O_W1 + 128 * LDW1 * 2;       // 52224
constexpr int O_T  = O_P  + 128 * LDP  * 2;       // 136192
// per-pipeline tile block
constexpr int H_E  = 0;                           // 16*72*2   = 2304
constexpr int H_H1 = H_E  + MT * LDE  * 2;        // 2304
constexpr int H_H2 = H_H1 + MT * LDH  * 2;        // 6656
constexpr int H_X  = H_H2 + MT * LDH  * 2;        // 11008
constexpr int HB   = H_X  + MT * LDXH * 2;        // 21504
constexpr int SMEM_BYTES = O_T + NPIPE * HB;      // 222208
}

__device__ __forceinline__ float silu_f(float x) {
    return __fdividef(x, 1.0f + __expf(-x));
}

using FragA  = wmma::fragment<wmma::matrix_a, 16, 16, 16, __half, wmma::row_major>;
using FragB  = wmma::fragment<wmma::matrix_b, 16, 16, 16, __half, wmma::row_major>;
using FragC  = wmma::fragment<wmma::accumulator, 16, 16, 16, float>;
using FragCH = wmma::fragment<wmma::accumulator, 16, 16, 16, __half>;

__device__ __forceinline__ void st_h4(__half* d, float4 v) {
    __half2 lo = __floats2half2_rn(v.x, v.y);
    __half2 hi = __floats2half2_rn(v.z, v.w);
    uint2 u;
    u.x = *reinterpret_cast<uint32_t*>(&lo);
    u.y = *reinterpret_cast<uint32_t*>(&hi);
    *reinterpret_cast<uint2*>(d) = u;
}
__device__ __forceinline__ void pbar(int id) {
    asm volatile("bar.sync %0, 128;" :: "r"(id) : "memory");
}

__global__ void __launch_bounds__(THREADS, 1)
fused_fp16(const float* __restrict__ emb, const float* __restrict__ x1,
           const float* __restrict__ x2, const float* __restrict__ W0,
           const float* __restrict__ W1,
           const float* __restrict__ P1, const float* __restrict__ P2,
           const float* __restrict__ P3, const float* __restrict__ P4,
           const float* __restrict__ P5, float* __restrict__ out)
{
    extern __shared__ char smc[];
    __half* sW0 = reinterpret_cast<__half*>(smc + O_W0);
    __half* sW1 = reinterpret_cast<__half*>(smc + O_W1);
    __half* sP  = reinterpret_cast<__half*>(smc + O_P);

    const int tid  = threadIdx.x;
    const int warp = tid >> 5;

    // ---------------- stage all weights once (full block) ----------------
    for (int q = tid; q < 64 * 32; q += THREADS) {
        int k = q >> 5, c4 = (q & 31) * 4;
        st_h4(sW0 + k * LDW0 + c4, *(const float4*)(W0 + k * 128 + c4));
    }
    for (int q = tid; q < 128 * 32; q += THREADS) {
        int k = q >> 5, c4 = (q & 31) * 4;
        st_h4(sW1 + k * LDW1 + c4, *(const float4*)(W1 + k * 128 + c4));
    }
    {
        const float* Ps[5] = {P1, P2, P3, P4, P5};
        for (int q = tid; q < 128 * 80; q += THREADS) {
            int k  = q / 80;
            int j4 = (q % 80) * 4;
            int c  = j4 / 160, jj = j4 % 160;
            int p  = jj >> 5,  uu = jj & 31;
            st_h4(sP + k * LDP + j4,
                  *(const float4*)(Ps[p] + k * 64 + c * 32 + uu));
        }
    }
    __syncthreads();

    // ---------------- per-pipeline setup ----------------
    const int pid  = warp >> 2;            // 0..3
    const int wl   = warp & 3;             // warp within pipeline
    const int ltid = tid & 127;            // thread within pipeline
    const int bid  = pid + 1;              // named barrier id 1..4

    char* hB = smc + O_T + pid * HB;
    __half* sE  = reinterpret_cast<__half*>(hB + H_E);
    __half* sH1 = reinterpret_cast<__half*>(hB + H_H1);
    __half* sH2 = reinterpret_cast<__half*>(hB + H_H2);
    __half* sXh = reinterpret_cast<__half*>(hB + H_X);

    // emb register double-buffer: 256 f4 per tile, thread covers ltid, ltid+128
    const int q0 = ltid, q1 = ltid + 128;
    const int er0 = q0 >> 4, ec0 = (q0 & 15) * 4;
    const int er1 = q1 >> 4, ec1 = (q1 & 15) * 4;
    float4 ea0, ea1;
    auto load_emb = [&](int t) {
        long g0 = (long)t * MT + er0;
        long g1 = (long)t * MT + er1;
        ea0 = *(const float4*)(emb + g0 * 64 + ec0);
        ea1 = *(const float4*)(emb + g1 * 64 + ec1);
    };

    const int w0 = blockIdx.x * NPIPE + pid;   // pipeline id 0..607
    if (w0 < TILES) load_emb(w0);

    const float s1  = 0.125f;
    const float s2  = 0.08838834764831845f;
    const float inv = 0.08838834764831845f;

    const float INV_SQRT2 = 0.7071067811865476f;
    const float INV_SQRT3 = 0.5773502691896258f;
    const float INV_SQRT6 = 0.4082482904638631f;

    for (int t = w0; t < TILES; t += NWORK) {
        // ---- STS emb tile; barrier also orders vs prior-tile epilogue ----
        st_h4(sE + er0 * LDE + ec0, ea0);
        st_h4(sE + er1 * LDE + ec1, ea1);
        pbar(bid);
        if (t + NWORK < TILES) load_emb(t + NWORK);

        // ---- G1: emb @ W0 -> silu in regs -> sH1 (fp16 direct) ----
        {
            FragC acc[2];
            #pragma unroll
            for (int n = 0; n < 2; n++) wmma::fill_fragment(acc[n], 0.0f);
            #pragma unroll
            for (int k = 0; k < 64; k += 16) {
                FragA a;
                wmma::load_matrix_sync(a, sE + k, LDE);
                #pragma unroll
                for (int n = 0; n < 2; n++) {
                    FragB b;
                    wmma::load_matrix_sync(b, sW0 + k * LDW0 + wl * 32 + n * 16, LDW0);
                    wmma::mma_sync(acc[n], a, b, acc[n]);
                }
            }
            #pragma unroll
            for (int n = 0; n < 2; n++) {
                FragCH ch;
                #pragma unroll
                for (int i = 0; i < acc[n].num_elements; i++)
                    ch.x[i] = __float2half(silu_f(acc[n].x[i] * s1));
                wmma::store_matrix_sync(sH1 + wl * 32 + n * 16, ch, LDH,
                                        wmma::mem_row_major);
            }
        }
        pbar(bid);

        // ---- G2: h1 @ W1 -> silu*inv in regs -> sH2 (fp16 direct) ----
        {
            FragC acc[2];
            #pragma unroll
            for (int n = 0; n < 2; n++) wmma::fill_fragment(acc[n], 0.0f);
            #pragma unroll
            for (int k = 0; k < 128; k += 16) {
                FragA a;
                wmma::load_matrix_sync(a, sH1 + k, LDH);
                #pragma unroll
                for (int n = 0; n < 2; n++) {
                    FragB b;
                    wmma::load_matrix_sync(b, sW1 + k * LDW1 + wl * 32 + n * 16, LDW1);
                    wmma::mma_sync(acc[n], a, b, acc[n]);
                }
            }
            #pragma unroll
            for (int n = 0; n < 2; n++) {
                FragCH ch;
                #pragma unroll
                for (int i = 0; i < acc[n].num_elements; i++)
                    ch.x[i] = __float2half(silu_f(acc[n].x[i] * s2) * inv);
                wmma::store_matrix_sync(sH2 + wl * 32 + n * 16, ch, LDH,
                                        wmma::mem_row_major);
            }
        }
        pbar(bid);

        // ---- G3 merged: w(all 320 cols) = h2 @ Pcat, fp16 out ----
        // 20 n-tiles over 4 warps = 5 each (balanced)
        {
            FragC acc[5];
            #pragma unroll
            for (int s = 0; s < 5; s++) wmma::fill_fragment(acc[s], 0.0f);
            #pragma unroll
            for (int k = 0; k < 128; k += 16) {
                FragA a;
                wmma::load_matrix_sync(a, sH2 + k, LDH);
                #pragma unroll
                for (int s = 0; s < 5; s++) {
                    int nt = wl + s * 4;
                    FragB b;
                    wmma::load_matrix_sync(b, sP + k * LDP + nt * 16, LDP);
                    wmma::mma_sync(acc[s], a, b, acc[s]);
                }
            }
            #pragma unroll
            for (int s = 0; s < 5; s++) {
                int nt = wl + s * 4;
                FragCH ch;
                #pragma unroll
                for (int i = 0; i < acc[s].num_elements; i++)
                    ch.x[i] = __float2half(acc[s].x[i]);
                wmma::store_matrix_sync(sXh + nt * 16, ch, LDXH,
                                        wmma::mem_row_major);
            }
        }
        pbar(bid);

        const long g0 = (long)t * MT;

        // ---- epilogue: two register-sized halves, no barrier between ----
        #pragma unroll
        for (int c = 0; c < 2; c++) {
            float x10v[4], av[12];
            float4 x2v[4];
            #pragma unroll
            for (int h = 0; h < 4; h++) {
                int idx = ltid + h * 128;         // 512 tasks: 16 rows x 32 u
                int r = idx >> 5, uu = idx & 31;
                int u = c * 32 + uu;
                long g = g0 + r;
                const float* x1r = x1 + g * 256;
                x10v[h]       = x1r[u];
                av[3 * h + 0] = x1r[64 + 3 * u + 0];
                av[3 * h + 1] = x1r[64 + 3 * u + 1];
                av[3 * h + 2] = x1r[64 + 3 * u + 2];
                x2v[h] = *(const float4*)(x2 + g * 4);
            }
            #pragma unroll
            for (int h = 0; h < 4; h++) {
                int idx = ltid + h * 128;
                int r = idx >> 5, uu = idx & 31;
                int u = c * 32 + uu;
                long g = g0 + r;

                float b0 = x2v[h].x, c0v = x2v[h].y, c1v = x2v[h].z, c2v = x2v[h].w;
                float x10 = x10v[h];
                float a0 = av[3 * h + 0], a1 = av[3 * h + 1], a2 = av[3 * h + 2];

                const __half* wr = sXh + r * LDXH + c * 160 + uu;
                float w1 = __half2float(wr[0]);
                float w2 = __half2float(wr[32]);
                float w3 = __half2float(wr[64]);
                float w4 = __half2float(wr[96]);
                float w5 = __half2float(wr[128]);

                float* o = out + g * 448;
                float dot = a0 * c0v + a1 * c1v + a2 * c2v;

                o[u] = INV_SQRT2 * (w1 * x10 * b0 + w4 * dot * INV_SQRT3);

                o[64 + 3 * u + 0] = INV_SQRT2 * (w2 * a0 * b0 + w3 * x10 * c0v);
                o[64 + 3 * u + 1] = INV_SQRT2 * (w2 * a1 * b0 + w3 * x10 * c1v);
                o[64 + 3 * u + 2] = INV_SQRT2 * (w2 * a2 * b0 + w3 * x10 * c2v);

                float r0 = a1 * c2v - a2 * c1v;
                float r1 = a2 * c0v - a0 * c2v;
                float r2 = a0 * c1v - a1 * c0v;
                o[256 + 3 * u + 0] = w5 * r0 * INV_SQRT6;
                o[256 + 3 * u + 1] = w5 * r1 * INV_SQRT6;
                o[256 + 3 * u + 2] = w5 * r2 * INV_SQRT6;
            }
        }
    }
}

extern "C" void kernel_launch(void* const* d_in, const int* in_sizes, int n_in,
                              void* d_out, int out_size) {
    (void)in_sizes; (void)n_in; (void)out_size;
    const float* emb = (const float*)d_in[0];
    const float* x1  = (const float*)d_in[1];
    const float* x2  = (const float*)d_in[2];
    const float* W0  = (const float*)d_in[3];
    const float* W1  = (const float*)d_in[4];
    const float* P1  = (const float*)d_in[5];
    const float* P2  = (const float*)d_in[6];
    const float* P3  = (const float*)d_in[7];
    const float* P4  = (const float*)d_in[8];
    const float* P5  = (const float*)d_in[9];
    float* out = (float*)d_out;

    cudaFuncSetAttribute(fused_fp16,
                         cudaFuncAttributeMaxDynamicSharedMemorySize, SMEM_BYTES);

    fused_fp16<<<NSM, THREADS, SMEM_BYTES>>>(emb, x1, x2, W0, W1,
                                             P1, P2, P3, P4, P5, out);
}

// round 15
// speedup vs baseline: 1.0451x; 1.0451x over previous
#include <cuda_runtime.h>
#include <cuda_fp16.h>
#include <mma.h>
#include <cstdint>

using namespace nvcuda;

namespace {
constexpr int E_TOT   = 100000;
constexpr int NSM     = 152;
constexpr int MT      = 16;                       // rows per pipeline tile
constexpr int TILES   = E_TOT / MT;               // 6250 exact
constexpr int NPIPE   = 4;
constexpr int NWORK   = NSM * NPIPE;              // 608 pipelines
constexpr int THREADS = 512;

// leading dims (elements)
constexpr int LDW0 = 136;   // halves
constexpr int LDW1 = 136;   // halves
constexpr int LDP  = 328;   // halves
constexpr int LDE  = 72;    // halves
constexpr int LDH  = 136;   // halves
constexpr int LDXH = 168;   // halves (w chunk buffer, fp16: 160 + 8 pad)

// byte offsets
constexpr int O_W0 = 0;                           // 17408
constexpr int O_W1 = O_W0 + 64  * LDW0 * 2;       // 17408
constexpr int O_P  = O_W1 + 128 * LDW1 * 2;       // 52224
constexpr int O_T  = O_P  + 128 * LDP  * 2;       // 136192
// per-pipeline tile block
constexpr int H_E  = 0;                           // 16*72*2   = 2304
constexpr int H_H1 = H_E  + MT * LDE  * 2;        // 2304
constexpr int H_H2 = H_H1 + MT * LDH  * 2;        // 6656
constexpr int H_X  = H_H2 + MT * LDH  * 2;        // 11008
constexpr int HB   = H_X  + MT * LDXH * 2;        // 16384
constexpr int SMEM_BYTES = O_T + NPIPE * HB;      // 201728
}

__device__ __forceinline__ float silu_f(float x) {
    return __fdividef(x, 1.0f + __expf(-x));
}

using FragA  = wmma::fragment<wmma::matrix_a, 16, 16, 16, __half, wmma::row_major>;
using FragB  = wmma::fragment<wmma::matrix_b, 16, 16, 16, __half, wmma::row_major>;
using FragC  = wmma::fragment<wmma::accumulator, 16, 16, 16, float>;
using FragCH = wmma::fragment<wmma::accumulator, 16, 16, 16, __half>;

__device__ __forceinline__ void st_h4(__half* d, float4 v) {
    __half2 lo = __floats2half2_rn(v.x, v.y);
    __half2 hi = __floats2half2_rn(v.z, v.w);
    uint2 u;
    u.x = *reinterpret_cast<uint32_t*>(&lo);
    u.y = *reinterpret_cast<uint32_t*>(&hi);
    *reinterpret_cast<uint2*>(d) = u;
}
__device__ __forceinline__ void pbar(int id) {
    asm volatile("bar.sync %0, 128;" :: "r"(id) : "memory");
}

__global__ void __launch_bounds__(THREADS, 1)
fused_fp16(const float* __restrict__ emb, const float* __restrict__ x1,
           const float* __restrict__ x2, const float* __restrict__ W0,
           const float* __restrict__ W1,
           const float* __restrict__ P1, const float* __restrict__ P2,
           const float* __restrict__ P3, const float* __restrict__ P4,
           const float* __restrict__ P5, float* __restrict__ out)
{
    extern __shared__ char smc[];
    __half* sW0 = reinterpret_cast<__half*>(smc + O_W0);
    __half* sW1 = reinterpret_cast<__half*>(smc + O_W1);
    __half* sP  = reinterpret_cast<__half*>(smc + O_P);

    const int tid  = threadIdx.x;
    const int warp = tid >> 5;

    // ---------------- stage all weights once (full block) ----------------
    for (int q = tid; q < 64 * 32; q += THREADS) {
        int k = q >> 5, c4 = (q & 31) * 4;
        st_h4(sW0 + k * LDW0 + c4, *(const float4*)(W0 + k * 128 + c4));
    }
    for (int q = tid; q < 128 * 32; q += THREADS) {
        int k = q >> 5, c4 = (q & 31) * 4;
        st_h4(sW1 + k * LDW1 + c4, *(const float4*)(W1 + k * 128 + c4));
    }
    {
        const float* Ps[5] = {P1, P2, P3, P4, P5};
        for (int q = tid; q < 128 * 80; q += THREADS) {
            int k  = q / 80;
            int j4 = (q % 80) * 4;
            int c  = j4 / 160, jj = j4 % 160;
            int p  = jj >> 5,  uu = jj & 31;
            st_h4(sP + k * LDP + j4,
                  *(const float4*)(Ps[p] + k * 64 + c * 32 + uu));
        }
    }
    __syncthreads();

    // ---------------- per-pipeline setup ----------------
    const int pid  = warp >> 2;            // 0..3
    const int wl   = warp & 3;             // warp within pipeline
    const int ltid = tid & 127;            // thread within pipeline
    const int bid  = pid + 1;              // named barrier id 1..4

    char* hB = smc + O_T + pid * HB;
    __half* sE  = reinterpret_cast<__half*>(hB + H_E);
    __half* sH1 = reinterpret_cast<__half*>(hB + H_H1);
    __half* sH2 = reinterpret_cast<__half*>(hB + H_H2);
    __half* sXh = reinterpret_cast<__half*>(hB + H_X);

    // emb register double-buffer: 256 f4 per tile, thread covers ltid, ltid+128
    const int q0 = ltid, q1 = ltid + 128;
    const int er0 = q0 >> 4, ec0 = (q0 & 15) * 4;
    const int er1 = q1 >> 4, ec1 = (q1 & 15) * 4;
    float4 ea0, ea1;
    auto load_emb = [&](int t) {
        long g0 = (long)t * MT + er0;
        long g1 = (long)t * MT + er1;
        ea0 = *(const float4*)(emb + g0 * 64 + ec0);
        ea1 = *(const float4*)(emb + g1 * 64 + ec1);
    };

    const int w0 = blockIdx.x * NPIPE + pid;   // pipeline id 0..607
    if (w0 < TILES) load_emb(w0);

    const float s1  = 0.125f;
    const float s2  = 0.08838834764831845f;
    const float inv = 0.08838834764831845f;

    const float INV_SQRT2 = 0.7071067811865476f;
    const float INV_SQRT3 = 0.5773502691896258f;
    const float INV_SQRT6 = 0.4082482904638631f;

    for (int t = w0; t < TILES; t += NWORK) {
        // ---- STS emb tile; barrier also fences prior epilogue sXh reads ----
        st_h4(sE + er0 * LDE + ec0, ea0);
        st_h4(sE + er1 * LDE + ec1, ea1);
        pbar(bid);
        if (t + NWORK < TILES) load_emb(t + NWORK);

        // ---- G1: emb @ W0 -> silu in regs -> sH1 (fp16 direct) ----
        {
            FragC acc[2];
            #pragma unroll
            for (int n = 0; n < 2; n++) wmma::fill_fragment(acc[n], 0.0f);
            #pragma unroll
            for (int k = 0; k < 64; k += 16) {
                FragA a;
                wmma::load_matrix_sync(a, sE + k, LDE);
                #pragma unroll
                for (int n = 0; n < 2; n++) {
                    FragB b;
                    wmma::load_matrix_sync(b, sW0 + k * LDW0 + wl * 32 + n * 16, LDW0);
                    wmma::mma_sync(acc[n], a, b, acc[n]);
                }
            }
            #pragma unroll
            for (int n = 0; n < 2; n++) {
                FragCH ch;
                #pragma unroll
                for (int i = 0; i < acc[n].num_elements; i++)
                    ch.x[i] = __float2half(silu_f(acc[n].x[i] * s1));
                wmma::store_matrix_sync(sH1 + wl * 32 + n * 16, ch, LDH,
                                        wmma::mem_row_major);
            }
        }
        pbar(bid);

        // ---- G2: h1 @ W1 -> silu*inv in regs -> sH2 (fp16 direct) ----
        {
            FragC acc[2];
            #pragma unroll
            for (int n = 0; n < 2; n++) wmma::fill_fragment(acc[n], 0.0f);
            #pragma unroll
            for (int k = 0; k < 128; k += 16) {
                FragA a;
                wmma::load_matrix_sync(a, sH1 + k, LDH);
                #pragma unroll
                for (int n = 0; n < 2; n++) {
                    FragB b;
                    wmma::load_matrix_sync(b, sW1 + k * LDW1 + wl * 32 + n * 16, LDW1);
                    wmma::mma_sync(acc[n], a, b, acc[n]);
                }
            }
            #pragma unroll
            for (int n = 0; n < 2; n++) {
                FragCH ch;
                #pragma unroll
                for (int i = 0; i < acc[n].num_elements; i++)
                    ch.x[i] = __float2half(silu_f(acc[n].x[i] * s2) * inv);
                wmma::store_matrix_sync(sH2 + wl * 32 + n * 16, ch, LDH,
                                        wmma::mem_row_major);
            }
        }
        pbar(bid);

        const long g0 = (long)t * MT;

        // ---- G3 + epilogue: 2 chunks of 160 cols (32 u each) ----
        #pragma unroll
        for (int c = 0; c < 2; c++) {
            // prefetch epilogue inputs (hide LDG under MMA)
            float x10v[4], av[12];
            float4 x2v[4];
            #pragma unroll
            for (int h = 0; h < 4; h++) {
                int idx = ltid + h * 128;         // 512 tasks: 16 rows x 32 u
                int r = idx >> 5, uu = idx & 31;
                int u = c * 32 + uu;
                long g = g0 + r;
                const float* x1r = x1 + g * 256;
                x10v[h]       = x1r[u];
                av[3 * h + 0] = x1r[64 + 3 * u + 0];
                av[3 * h + 1] = x1r[64 + 3 * u + 1];
                av[3 * h + 2] = x1r[64 + 3 * u + 2];
                x2v[h] = *(const float4*)(x2 + g * 4);
            }

            {   // w = h2 @ Pcat[c] : 10 n-tiles over 4 warps (3/3/2/2), fp16 out
                const int ncnt = (wl < 2) ? 3 : 2;
                FragC acc[3];
                for (int s = 0; s < ncnt; s++) wmma::fill_fragment(acc[s], 0.0f);
                #pragma unroll
                for (int k = 0; k < 128; k += 16) {
                    FragA a;
                    wmma::load_matrix_sync(a, sH2 + k, LDH);
                    for (int s = 0; s < ncnt; s++) {
                        int nt = wl + s * 4;
                        FragB b;
                        wmma::load_matrix_sync(b, sP + k * LDP + c * 160 + nt * 16, LDP);
                        wmma::mma_sync(acc[s], a, b, acc[s]);
                    }
                }
                for (int s = 0; s < ncnt; s++) {
                    int nt = wl + s * 4;
                    FragCH ch;
                    #pragma unroll
                    for (int i = 0; i < ch.num_elements; i++)
                        ch.x[i] = __float2half(acc[s].x[i]);
                    wmma::store_matrix_sync(sXh + nt * 16, ch, LDXH,
                                            wmma::mem_row_major);
                }
            }
            pbar(bid);

            // ---- epilogue ----
            #pragma unroll
            for (int h = 0; h < 4; h++) {
                int idx = ltid + h * 128;
                int r = idx >> 5, uu = idx & 31;
                int u = c * 32 + uu;
                long g = g0 + r;

                float b0 = x2v[h].x, c0v = x2v[h].y, c1v = x2v[h].z, c2v = x2v[h].w;
                float x10 = x10v[h];
                float a0 = av[3 * h + 0], a1 = av[3 * h + 1], a2 = av[3 * h + 2];

                const __half* wr = sXh + r * LDXH + uu;
                float w1 = __half2float(wr[0]);
                float w2 = __half2float(wr[32]);
                float w3 = __half2float(wr[64]);
                float w4 = __half2float(wr[96]);
                float w5 = __half2float(wr[128]);

                float* o = out + g * 448;
                float dot = a0 * c0v + a1 * c1v + a2 * c2v;

                o[u] = INV_SQRT2 * (w1 * x10 * b0 + w4 * dot * INV_SQRT3);

                o[64 + 3 * u + 0] = INV_SQRT2 * (w2 * a0 * b0 + w3 * x10 * c0v);
                o[64 + 3 * u + 1] = INV_SQRT2 * (w2 * a1 * b0 + w3 * x10 * c1v);
                o[64 + 3 * u + 2] = INV_SQRT2 * (w2 * a2 * b0 + w3 * x10 * c2v);

                float r0 = a1 * c2v - a2 * c1v;
                float r1 = a2 * c0v - a0 * c2v;
                float r2 = a0 * c1v - a1 * c0v;
                o[256 + 3 * u + 0] = w5 * r0 * INV_SQRT6;
                o[256 + 3 * u + 1] = w5 * r1 * INV_SQRT6;
                o[256 + 3 * u + 2] = w5 * r2 * INV_SQRT6;
            }
            if (c == 0) pbar(bid);   // sXh reused by chunk 1; loop-top barrier fences chunk-1 reads
        }
    }
}

extern "C" void kernel_launch(void* const* d_in, const int* in_sizes, int n_in,
                              void* d_out, int out_size) {
    (void)in_sizes; (void)n_in; (void)out_size;
    const float* emb = (const float*)d_in[0];
    const float* x1  = (const float*)d_in[1];
    const float* x2  = (const float*)d_in[2];
    const float* W0  = (const float*)d_in[3];
    const float* W1  = (const float*)d_in[4];
    const float* P1  = (const float*)d_in[5];
    const float* P2  = (const float*)d_in[6];
    const float* P3  = (const float*)d_in[7];
    const float* P4  = (const float*)d_in[8];
    const float* P5  = (const float*)d_in[9];
    float* out = (float*)d_out;

    cudaFuncSetAttribute(fused_fp16,
                         cudaFuncAttributeMaxDynamicSharedMemorySize, SMEM_BYTES);

    fused_fp16<<<NSM, THREADS, SMEM_BYTES>>>(emb, x1, x2, W0, W1,
                                             P1, P2, P3, P4, P5, out);
}

// round 16
// speedup vs baseline: 1.0515x; 1.0060x over previous
#include <cuda_runtime.h>
#include <cuda_fp16.h>
#include <mma.h>
#include <cstdint>

using namespace nvcuda;

namespace {
constexpr int E_TOT   = 100000;
constexpr int NSM     = 152;
constexpr int MT      = 16;                       // rows per pipeline tile
constexpr int TILES   = E_TOT / MT;               // 6250 exact
constexpr int NPIPE   = 5;
constexpr int NWORK   = NSM * NPIPE;              // 760 pipelines
constexpr int THREADS = 128 * NPIPE;              // 640

// leading dims (elements)
constexpr int LDW0 = 136;   // halves
constexpr int LDW1 = 136;   // halves
constexpr int LDP  = 328;   // halves
constexpr int LDE  = 72;    // halves
constexpr int LDH  = 136;   // halves
constexpr int LDXH = 168;   // halves (w chunk buffer, fp16: 160 + 8 pad)

// byte offsets
constexpr int O_W0 = 0;                           // 17408
constexpr int O_W1 = O_W0 + 64  * LDW0 * 2;       // 17408
constexpr int O_P  = O_W1 + 128 * LDW1 * 2;       // 52224
constexpr int O_T  = O_P  + 128 * LDP  * 2;       // 136192
// per-pipeline tile block
constexpr int H_E  = 0;                           // 16*72*2   = 2304
constexpr int H_H1 = H_E  + MT * LDE  * 2;        // 2304
constexpr int H_H2 = H_H1 + MT * LDH  * 2;        // 6656
constexpr int H_X  = H_H2 + MT * LDH  * 2;        // 11008
constexpr int HB   = H_X  + MT * LDXH * 2;        // 16384
constexpr int SMEM_BYTES = O_T + NPIPE * HB;      // 218112
}

__device__ __forceinline__ float silu_f(float x) {
    return __fdividef(x, 1.0f + __expf(-x));
}

using FragA  = wmma::fragment<wmma::matrix_a, 16, 16, 16, __half, wmma::row_major>;
using FragB  = wmma::fragment<wmma::matrix_b, 16, 16, 16, __half, wmma::row_major>;
using FragC  = wmma::fragment<wmma::accumulator, 16, 16, 16, float>;
using FragCH = wmma::fragment<wmma::accumulator, 16, 16, 16, __half>;

__device__ __forceinline__ void st_h4(__half* d, float4 v) {
    __half2 lo = __floats2half2_rn(v.x, v.y);
    __half2 hi = __floats2half2_rn(v.z, v.w);
    uint2 u;
    u.x = *reinterpret_cast<uint32_t*>(&lo);
    u.y = *reinterpret_cast<uint32_t*>(&hi);
    *reinterpret_cast<uint2*>(d) = u;
}
__device__ __forceinline__ void pbar(int id) {
    asm volatile("bar.sync %0, 128;" :: "r"(id) : "memory");
}

__global__ void __launch_bounds__(THREADS, 1)
fused_fp16(const float* __restrict__ emb, const float* __restrict__ x1,
           const float* __restrict__ x2, const float* __restrict__ W0,
           const float* __restrict__ W1,
           const float* __restrict__ P1, const float* __restrict__ P2,
           const float* __restrict__ P3, const float* __restrict__ P4,
           const float* __restrict__ P5, float* __restrict__ out)
{
    extern __shared__ char smc[];
    __half* sW0 = reinterpret_cast<__half*>(smc + O_W0);
    __half* sW1 = reinterpret_cast<__half*>(smc + O_W1);
    __half* sP  = reinterpret_cast<__half*>(smc + O_P);

    const int tid  = threadIdx.x;
    const int warp = tid >> 5;

    // ---------------- stage all weights once (full block) ----------------
    for (int q = tid; q < 64 * 32; q += THREADS) {
        int k = q >> 5, c4 = (q & 31) * 4;
        st_h4(sW0 + k * LDW0 + c4, *(const float4*)(W0 + k * 128 + c4));
    }
    for (int q = tid; q < 128 * 32; q += THREADS) {
        int k = q >> 5, c4 = (q & 31) * 4;
        st_h4(sW1 + k * LDW1 + c4, *(const float4*)(W1 + k * 128 + c4));
    }
    {
        const float* Ps[5] = {P1, P2, P3, P4, P5};
        for (int q = tid; q < 128 * 80; q += THREADS) {
            int k  = q / 80;
            int j4 = (q % 80) * 4;
            int c  = j4 / 160, jj = j4 % 160;
            int p  = jj >> 5,  uu = jj & 31;
            st_h4(sP + k * LDP + j4,
                  *(const float4*)(Ps[p] + k * 64 + c * 32 + uu));
        }
    }
    __syncthreads();

    // ---------------- per-pipeline setup ----------------
    const int pid  = warp >> 2;            // 0..4
    const int wl   = warp & 3;             // warp within pipeline
    const int ltid = tid & 127;            // thread within pipeline
    const int bid  = pid + 1;              // named barrier id 1..5

    char* hB = smc + O_T + pid * HB;
    __half* sE  = reinterpret_cast<__half*>(hB + H_E);
    __half* sH1 = reinterpret_cast<__half*>(hB + H_H1);
    __half* sH2 = reinterpret_cast<__half*>(hB + H_H2);
    __half* sXh = reinterpret_cast<__half*>(hB + H_X);

    // emb register double-buffer: 256 f4 per tile, thread covers ltid, ltid+128
    const int q0 = ltid, q1 = ltid + 128;
    const int er0 = q0 >> 4, ec0 = (q0 & 15) * 4;
    const int er1 = q1 >> 4, ec1 = (q1 & 15) * 4;
    float4 ea0, ea1;
    auto load_emb = [&](int t) {
        long g0 = (long)t * MT + er0;
        long g1 = (long)t * MT + er1;
        ea0 = *(const float4*)(emb + g0 * 64 + ec0);
        ea1 = *(const float4*)(emb + g1 * 64 + ec1);
    };

    const int w0 = blockIdx.x * NPIPE + pid;   // pipeline id 0..759
    if (w0 < TILES) load_emb(w0);

    const float s1  = 0.125f;
    const float s2  = 0.08838834764831845f;
    const float inv = 0.08838834764831845f;

    const float INV_SQRT2 = 0.7071067811865476f;
    const float INV_SQRT3 = 0.5773502691896258f;
    const float INV_SQRT6 = 0.4082482904638631f;

    for (int t = w0; t < TILES; t += NWORK) {
        // ---- STS emb tile; barrier also fences prior epilogue sXh reads ----
        st_h4(sE + er0 * LDE + ec0, ea0);
        st_h4(sE + er1 * LDE + ec1, ea1);
        pbar(bid);
        if (t + NWORK < TILES) load_emb(t + NWORK);

        // ---- G1: emb @ W0 -> silu in regs -> sH1 (fp16 direct) ----
        {
            FragC acc[2];
            #pragma unroll
            for (int n = 0; n < 2; n++) wmma::fill_fragment(acc[n], 0.0f);
            #pragma unroll
            for (int k = 0; k < 64; k += 16) {
                FragA a;
                wmma::load_matrix_sync(a, sE + k, LDE);
                #pragma unroll
                for (int n = 0; n < 2; n++) {
                    FragB b;
                    wmma::load_matrix_sync(b, sW0 + k * LDW0 + wl * 32 + n * 16, LDW0);
                    wmma::mma_sync(acc[n], a, b, acc[n]);
                }
            }
            #pragma unroll
            for (int n = 0; n < 2; n++) {
                FragCH ch;
                #pragma unroll
                for (int i = 0; i < acc[n].num_elements; i++)
                    ch.x[i] = __float2half(silu_f(acc[n].x[i] * s1));
                wmma::store_matrix_sync(sH1 + wl * 32 + n * 16, ch, LDH,
                                        wmma::mem_row_major);
            }
        }
        pbar(bid);

        // ---- G2: h1 @ W1 -> silu*inv in regs -> sH2 (fp16 direct) ----
        {
            FragC acc[2];
            #pragma unroll
            for (int n = 0; n < 2; n++) wmma::fill_fragment(acc[n], 0.0f);
            #pragma unroll
            for (int k = 0; k < 128; k += 16) {
                FragA a;
                wmma::load_matrix_sync(a, sH1 + k, LDH);
                #pragma unroll
                for (int n = 0; n < 2; n++) {
                    FragB b;
                    wmma::load_matrix_sync(b, sW1 + k * LDW1 + wl * 32 + n * 16, LDW1);
                    wmma::mma_sync(acc[n], a, b, acc[n]);
                }
            }
            #pragma unroll
            for (int n = 0; n < 2; n++) {
                FragCH ch;
                #pragma unroll
                for (int i = 0; i < acc[n].num_elements; i++)
                    ch.x[i] = __float2half(silu_f(acc[n].x[i] * s2) * inv);
                wmma::store_matrix_sync(sH2 + wl * 32 + n * 16, ch, LDH,
                                        wmma::mem_row_major);
            }
        }
        pbar(bid);

        const long g0 = (long)t * MT;

        // ---- G3 + epilogue: 2 chunks of 160 cols (32 u each) ----
        #pragma unroll
        for (int c = 0; c < 2; c++) {
            // prefetch x1 only (the DRAM-latency stream); x2 is L1/L2-hot
            float x10v[4], av[12];
            #pragma unroll
            for (int h = 0; h < 4; h++) {
                int idx = ltid + h * 128;         // 512 tasks: 16 rows x 32 u
                int r = idx >> 5, uu = idx & 31;
                int u = c * 32 + uu;
                long g = g0 + r;
                const float* x1r = x1 + g * 256;
                x10v[h]       = x1r[u];
                av[3 * h + 0] = x1r[64 + 3 * u + 0];
                av[3 * h + 1] = x1r[64 + 3 * u + 1];
                av[3 * h + 2] = x1r[64 + 3 * u + 2];
            }

            {   // w = h2 @ Pcat[c] : 10 n-tiles over 4 warps (3/3/2/2), fp16 out
                const int ncnt = (wl < 2) ? 3 : 2;
                FragC acc[3];
                for (int s = 0; s < ncnt; s++) wmma::fill_fragment(acc[s], 0.0f);
                #pragma unroll
                for (int k = 0; k < 128; k += 16) {
                    FragA a;
                    wmma::load_matrix_sync(a, sH2 + k, LDH);
                    for (int s = 0; s < ncnt; s++) {
                        int nt = wl + s * 4;
                        FragB b;
                        wmma::load_matrix_sync(b, sP + k * LDP + c * 160 + nt * 16, LDP);
                        wmma::mma_sync(acc[s], a, b, acc[s]);
                    }
                }
                for (int s = 0; s < ncnt; s++) {
                    int nt = wl + s * 4;
                    FragCH ch;
                    #pragma unroll
                    for (int i = 0; i < ch.num_elements; i++)
                        ch.x[i] = __float2half(acc[s].x[i]);
                    wmma::store_matrix_sync(sXh + nt * 16, ch, LDXH,
                                            wmma::mem_row_major);
                }
            }
            pbar(bid);

            // ---- epilogue (x2 loaded inline; hot in cache) ----
            #pragma unroll
            for (int h = 0; h < 4; h++) {
                int idx = ltid + h * 128;
                int r = idx >> 5, uu = idx & 31;
                int u = c * 32 + uu;
                long g = g0 + r;

                float4 t2 = *(const float4*)(x2 + g * 4);
                float b0 = t2.x, c0v = t2.y, c1v = t2.z, c2v = t2.w;
                float x10 = x10v[h];
                float a0 = av[3 * h + 0], a1 = av[3 * h + 1], a2 = av[3 * h + 2];

                const __half* wr = sXh + r * LDXH + uu;
                float w1 = __half2float(wr[0]);
                float w2 = __half2float(wr[32]);
                float w3 = __half2float(wr[64]);
                float w4 = __half2float(wr[96]);
                float w5 = __half2float(wr[128]);

                float* o = out + g * 448;
                float dot = a0 * c0v + a1 * c1v + a2 * c2v;

                o[u] = INV_SQRT2 * (w1 * x10 * b0 + w4 * dot * INV_SQRT3);

                o[64 + 3 * u + 0] = INV_SQRT2 * (w2 * a0 * b0 + w3 * x10 * c0v);
                o[64 + 3 * u + 1] = INV_SQRT2 * (w2 * a1 * b0 + w3 * x10 * c1v);
                o[64 + 3 * u + 2] = INV_SQRT2 * (w2 * a2 * b0 + w3 * x10 * c2v);

                float r0 = a1 * c2v - a2 * c1v;
                float r1 = a2 * c0v - a0 * c2v;
                float r2 = a0 * c1v - a1 * c0v;
                o[256 + 3 * u + 0] = w5 * r0 * INV_SQRT6;
                o[256 + 3 * u + 1] = w5 * r1 * INV_SQRT6;
                o[256 + 3 * u + 2] = w5 * r2 * INV_SQRT6;
            }
            if (c == 0) pbar(bid);   // sXh reused by chunk 1; loop-top barrier fences chunk-1 reads
        }
    }
}

extern "C" void kernel_launch(void* const* d_in, const int* in_sizes, int n_in,
                              void* d_out, int out_size) {
    (void)in_sizes; (void)n_in; (void)out_size;
    const float* emb = (const float*)d_in[0];
    const float* x1  = (const float*)d_in[1];
    const float* x2  = (const float*)d_in[2];
    const float* W0  = (const float*)d_in[3];
    const float* W1  = (const float*)d_in[4];
    const float* P1  = (const float*)d_in[5];
    const float* P2  = (const float*)d_in[6];
    const float* P3  = (const float*)d_in[7];
    const float* P4  = (const float*)d_in[8];
    const float* P5  = (const float*)d_in[9];
    float* out = (float*)d_out;

    cudaFuncSetAttribute(fused_fp16,
                         cudaFuncAttributeMaxDynamicSharedMemorySize, SMEM_BYTES);

    fused_fp16<<<NSM, THREADS, SMEM_BYTES>>>(emb, x1, x2, W0, W1,
                                             P1, P2, P3, P4, P5, out);
}